// round 2
// baseline (speedup 1.0000x reference)
#include <cuda_runtime.h>
#include <math.h>

#define E_ 8
#define H_ 2048
#define F_ 1024
#define D_ 2048
#define T_ 2048
#define TOPK_ 4
#define R_ 8
#define SCALING_ 2.0f
#define LIMIT_ 7.0f
#define ACT_ALPHA_ 1.702f

// Scratch (static __device__ globals — allocation-free per harness rules)
__device__ float g_w[E_ * T_];                       // 64 KB  routing weight per (e,t)
__device__ float g_xa[E_ * T_ * R_];                 // 512 KB x @ lora_gate_up_A
__device__ float g_la2[E_ * T_ * R_];                // 512 KB gatedw @ lora_down_A
__device__ float g_gatedw[(size_t)E_ * T_ * F_];     // 64 MB  w * activated intermediate

// ---------------------------------------------------------------------------
// K0: routing weights  w[e,t] = sum_k rw[t,k] * (idx[t,k]==e)
// NOTE: router_indices is int32 on device (JAX x64 disabled -> int64 request
// silently yields int32).
// ---------------------------------------------------------------------------
__global__ void k_route(const float* __restrict__ rw, const int* __restrict__ idx) {
    int t = blockIdx.x * blockDim.x + threadIdx.x;
    if (t >= T_) return;
    float acc[E_];
#pragma unroll
    for (int j = 0; j < E_; j++) acc[j] = 0.0f;
    for (int k = 0; k < TOPK_; k++) {
        int e = idx[t * TOPK_ + k];
        float v = rw[t * TOPK_ + k];
#pragma unroll
        for (int j = 0; j < E_; j++)
            if (j == e) acc[j] += v;
    }
#pragma unroll
    for (int j = 0; j < E_; j++) g_w[j * T_ + t] = acc[j];
}

// ---------------------------------------------------------------------------
// K1: g_xa[e,t,r] = sum_h x[t,h] * A1[e,h,r]      (warp per (e,t) row)
// ---------------------------------------------------------------------------
__global__ void k_loraA1(const float* __restrict__ X, const float* __restrict__ A1) {
    int warp = (blockIdx.x * blockDim.x + threadIdx.x) >> 5;
    int lane = threadIdx.x & 31;
    if (warp >= E_ * T_) return;
    int e = warp / T_;
    int t = warp % T_;
    const float* xrow = X + (size_t)t * H_;
    float acc[R_];
#pragma unroll
    for (int r = 0; r < R_; r++) acc[r] = 0.0f;
    for (int h = lane; h < H_; h += 32) {
        float xv = xrow[h];
        const float* arow = A1 + ((size_t)e * H_ + h) * R_;
#pragma unroll
        for (int r = 0; r < R_; r++) acc[r] += xv * arow[r];
    }
    float keep = 0.0f;
#pragma unroll
    for (int r = 0; r < R_; r++) {
        float v = acc[r];
#pragma unroll
        for (int off = 16; off; off >>= 1) v += __shfl_xor_sync(0xffffffff, v, off);
        if (lane == r) keep = v;
    }
    if (lane < R_) g_xa[(size_t)(e * T_ + t) * R_ + lane] = keep;
}

// ---------------------------------------------------------------------------
// K3: g_la2[e,t,r] = sum_f gatedw[e,t,f] * A2[e,f,r]   (warp per (e,t) row)
// ---------------------------------------------------------------------------
__global__ void k_loraA2(const float* __restrict__ A2) {
    int warp = (blockIdx.x * blockDim.x + threadIdx.x) >> 5;
    int lane = threadIdx.x & 31;
    if (warp >= E_ * T_) return;
    int e = warp / T_;
    int t = warp % T_;
    const float* xrow = g_gatedw + (size_t)(e * T_ + t) * F_;
    float acc[R_];
#pragma unroll
    for (int r = 0; r < R_; r++) acc[r] = 0.0f;
    for (int f = lane; f < F_; f += 32) {
        float xv = xrow[f];
        const float* arow = A2 + ((size_t)e * F_ + f) * R_;
#pragma unroll
        for (int r = 0; r < R_; r++) acc[r] += xv * arow[r];
    }
    float keep = 0.0f;
#pragma unroll
    for (int r = 0; r < R_; r++) {
        float v = acc[r];
#pragma unroll
        for (int off = 16; off; off >>= 1) v += __shfl_xor_sync(0xffffffff, v, off);
        if (lane == r) keep = v;
    }
    if (lane < R_) g_la2[(size_t)(e * T_ + t) * R_ + lane] = keep;
}

// ---------------------------------------------------------------------------
// K2: fused GEMM1 + LoRA + bias + GLU + routing-weight fold
//     gatedw[e,t,f] = w[e,t] * (up+1) * glu   for d-pairs (2f, 2f+1)
// grid: (D/128, T/128, E), 256 threads, 8x8 micro-tiles, BK=16
// ---------------------------------------------------------------------------
__global__ void __launch_bounds__(256)
k_gemm1(const float* __restrict__ X, const float* __restrict__ W,
        const float* __restrict__ bias, const float* __restrict__ B1) {
    __shared__ float As[16][128];
    __shared__ float Bs[16][128];

    int e  = blockIdx.z;
    int m0 = blockIdx.y * 128;
    int n0 = blockIdx.x * 128;
    int tid = threadIdx.x;
    int tx = tid & 15, ty = tid >> 4;

    float acc[8][8];
#pragma unroll
    for (int i = 0; i < 8; i++)
#pragma unroll
        for (int j = 0; j < 8; j++) acc[i][j] = 0.0f;

    const float* Wbase = W + (size_t)e * H_ * D_;

    for (int k0 = 0; k0 < H_; k0 += 16) {
#pragma unroll
        for (int i = 0; i < 2; i++) {
            int id  = tid * 2 + i;        // 0..511
            int row = id >> 2;            // 0..127
            int c4  = id & 3;             // 0..3
            float4 v = *(const float4*)(X + (size_t)(m0 + row) * H_ + k0 + c4 * 4);
            As[c4 * 4 + 0][row] = v.x;
            As[c4 * 4 + 1][row] = v.y;
            As[c4 * 4 + 2][row] = v.z;
            As[c4 * 4 + 3][row] = v.w;
        }
#pragma unroll
        for (int i = 0; i < 2; i++) {
            int id = tid * 2 + i;
            int kr = id >> 5;             // 0..15
            int c4 = id & 31;             // 0..31
            *(float4*)(&Bs[kr][c4 * 4]) =
                *(const float4*)(Wbase + (size_t)(k0 + kr) * D_ + n0 + c4 * 4);
        }
        __syncthreads();
#pragma unroll
        for (int kk = 0; kk < 16; kk++) {
            float a[8], b[8];
            *(float4*)(a)     = *(float4*)(&As[kk][ty * 8]);
            *(float4*)(a + 4) = *(float4*)(&As[kk][ty * 8 + 4]);
            *(float4*)(b)     = *(float4*)(&Bs[kk][tx * 8]);
            *(float4*)(b + 4) = *(float4*)(&Bs[kk][tx * 8 + 4]);
#pragma unroll
            for (int i = 0; i < 8; i++)
#pragma unroll
                for (int j = 0; j < 8; j++) acc[i][j] += a[i] * b[j];
        }
        __syncthreads();
    }

    int trow0 = m0 + ty * 8;
    int d0    = n0 + tx * 8;

    // rank-8 LoRA epilogue: acc += SCALING * xa[t,r] * B1[e,r,d]
#pragma unroll
    for (int r = 0; r < R_; r++) {
        float b1[8];
        *(float4*)(b1)     = *(const float4*)(B1 + ((size_t)e * R_ + r) * D_ + d0);
        *(float4*)(b1 + 4) = *(const float4*)(B1 + ((size_t)e * R_ + r) * D_ + d0 + 4);
#pragma unroll
        for (int i = 0; i < 8; i++) {
            float xav = g_xa[(size_t)(e * T_ + trow0 + i) * R_ + r] * SCALING_;
#pragma unroll
            for (int j = 0; j < 8; j++) acc[i][j] += xav * b1[j];
        }
    }

    float bj[8];
    *(float4*)(bj)     = *(const float4*)(bias + (size_t)e * D_ + d0);
    *(float4*)(bj + 4) = *(const float4*)(bias + (size_t)e * D_ + d0 + 4);

#pragma unroll
    for (int i = 0; i < 8; i++) {
        int t = trow0 + i;
        float wt = g_w[e * T_ + t];
        float res[4];
#pragma unroll
        for (int jp = 0; jp < 4; jp++) {
            float g = acc[i][2 * jp]     + bj[2 * jp];
            float u = acc[i][2 * jp + 1] + bj[2 * jp + 1];
            g = fminf(g, LIMIT_);
            u = fminf(fmaxf(u, -LIMIT_), LIMIT_);
            float glu = g / (1.0f + expf(-ACT_ALPHA_ * g));
            res[jp] = wt * (u + 1.0f) * glu;
        }
        *(float4*)(&g_gatedw[((size_t)e * T_ + t) * F_ + (d0 >> 1)]) =
            make_float4(res[0], res[1], res[2], res[3]);
    }
}

// ---------------------------------------------------------------------------
// K4: fused GEMM2 over all experts + LoRA + weighted bias
//     out[t,h] = sum_e { gatedw[e,t,:] @ down[e,:,h]
//                        + SCALING * la2[e,t,:] @ B2[e,:,h]
//                        + w[e,t] * bias2[e,h] }
// grid: (H/128, T/128), 256 threads
// ---------------------------------------------------------------------------
__global__ void __launch_bounds__(256)
k_gemm2(const float* __restrict__ Wd, const float* __restrict__ bias2,
        const float* __restrict__ B2, float* __restrict__ out) {
    __shared__ float As[16][128];
    __shared__ float Bs[16][128];

    int m0 = blockIdx.y * 128;   // token
    int n0 = blockIdx.x * 128;   // hidden
    int tid = threadIdx.x;
    int tx = tid & 15, ty = tid >> 4;

    float acc[8][8];
#pragma unroll
    for (int i = 0; i < 8; i++)
#pragma unroll
        for (int j = 0; j < 8; j++) acc[i][j] = 0.0f;

    int trow0 = m0 + ty * 8;
    int h0    = n0 + tx * 8;

    for (int e = 0; e < E_; e++) {
        const float* Arow  = g_gatedw + (size_t)e * T_ * F_;
        const float* Wbase = Wd + (size_t)e * F_ * H_;

        for (int k0 = 0; k0 < F_; k0 += 16) {
#pragma unroll
            for (int i = 0; i < 2; i++) {
                int id  = tid * 2 + i;
                int row = id >> 2;
                int c4  = id & 3;
                float4 v = *(const float4*)(Arow + (size_t)(m0 + row) * F_ + k0 + c4 * 4);
                As[c4 * 4 + 0][row] = v.x;
                As[c4 * 4 + 1][row] = v.y;
                As[c4 * 4 + 2][row] = v.z;
                As[c4 * 4 + 3][row] = v.w;
            }
#pragma unroll
            for (int i = 0; i < 2; i++) {
                int id = tid * 2 + i;
                int kr = id >> 5;
                int c4 = id & 31;
                *(float4*)(&Bs[kr][c4 * 4]) =
                    *(const float4*)(Wbase + (size_t)(k0 + kr) * H_ + n0 + c4 * 4);
            }
            __syncthreads();
#pragma unroll
            for (int kk = 0; kk < 16; kk++) {
                float a[8], b[8];
                *(float4*)(a)     = *(float4*)(&As[kk][ty * 8]);
                *(float4*)(a + 4) = *(float4*)(&As[kk][ty * 8 + 4]);
                *(float4*)(b)     = *(float4*)(&Bs[kk][tx * 8]);
                *(float4*)(b + 4) = *(float4*)(&Bs[kk][tx * 8 + 4]);
#pragma unroll
                for (int i = 0; i < 8; i++)
#pragma unroll
                    for (int j = 0; j < 8; j++) acc[i][j] += a[i] * b[j];
            }
            __syncthreads();
        }

        // per-expert epilogue: LoRA down + weighted bias
#pragma unroll
        for (int r = 0; r < R_; r++) {
            float b2[8];
            *(float4*)(b2)     = *(const float4*)(B2 + ((size_t)e * R_ + r) * H_ + h0);
            *(float4*)(b2 + 4) = *(const float4*)(B2 + ((size_t)e * R_ + r) * H_ + h0 + 4);
#pragma unroll
            for (int i = 0; i < 8; i++) {
                float la = g_la2[(size_t)(e * T_ + trow0 + i) * R_ + r] * SCALING_;
#pragma unroll
                for (int j = 0; j < 8; j++) acc[i][j] += la * b2[j];
            }
        }
        float bj[8];
        *(float4*)(bj)     = *(const float4*)(bias2 + (size_t)e * H_ + h0);
        *(float4*)(bj + 4) = *(const float4*)(bias2 + (size_t)e * H_ + h0 + 4);
#pragma unroll
        for (int i = 0; i < 8; i++) {
            float wt = g_w[e * T_ + trow0 + i];
#pragma unroll
            for (int j = 0; j < 8; j++) acc[i][j] += wt * bj[j];
        }
    }

#pragma unroll
    for (int i = 0; i < 8; i++) {
        *(float4*)(out + (size_t)(trow0 + i) * H_ + h0)     =
            make_float4(acc[i][0], acc[i][1], acc[i][2], acc[i][3]);
        *(float4*)(out + (size_t)(trow0 + i) * H_ + h0 + 4) =
            make_float4(acc[i][4], acc[i][5], acc[i][6], acc[i][7]);
    }
}

// ---------------------------------------------------------------------------
extern "C" void kernel_launch(void* const* d_in, const int* in_sizes, int n_in,
                              void* d_out, int out_size) {
    const float* x      = (const float*)d_in[0];   // [B,S,H] = [T,H]
    const float* rw     = (const float*)d_in[1];   // [T,K]
    const float* gup    = (const float*)d_in[2];   // [E,H,D]
    const float* gup_b  = (const float*)d_in[3];   // [E,D]
    const float* dn     = (const float*)d_in[4];   // [E,F,H]
    const float* dn_b   = (const float*)d_in[5];   // [E,H]
    const float* A1     = (const float*)d_in[6];   // [E,H,R]
    const float* B1     = (const float*)d_in[7];   // [E,R,D]
    const float* A2     = (const float*)d_in[8];   // [E,F,R]
    const float* B2     = (const float*)d_in[9];   // [E,R,H]
    const int*   ri     = (const int*)d_in[10];    // [T,K] int32 (JAX x64 off)
    float* out = (float*)d_out;

    k_route<<<(T_ + 127) / 128, 128>>>(rw, ri);
    k_loraA1<<<(E_ * T_) / 8, 256>>>(x, A1);                 // 8 warps/block
    k_gemm1<<<dim3(D_ / 128, T_ / 128, E_), 256>>>(x, gup, gup_b, B1);
    k_loraA2<<<(E_ * T_) / 8, 256>>>(A2);
    k_gemm2<<<dim3(H_ / 128, T_ / 128), 256>>>(dn, dn_b, B2, out);
}

// round 4
// speedup vs baseline: 1.9415x; 1.9415x over previous
#include <cuda_runtime.h>
#include <cuda_bf16.h>
#include <cstdint>
#include <math.h>

#define E_ 8
#define H_ 2048
#define F_ 1024
#define D_ 2048
#define T_ 2048
#define TOPK_ 4
#define R_ 8
#define SCALING_ 2.0f
#define LIMIT_ 7.0f
#define ACT_ALPHA_ 1.702f

// ---- scratch (__device__ globals; allocation-free per harness rules) ----
__device__ float g_w[E_ * T_];
__device__ float g_xa[E_ * T_ * R_];
__device__ float g_la2[E_ * T_ * R_];
__device__ __nv_bfloat16 g_xhi[(size_t)T_ * H_];
__device__ __nv_bfloat16 g_xlo[(size_t)T_ * H_];
__device__ __nv_bfloat16 g_w1hi[(size_t)E_ * D_ * H_];   // gate_up^T [e][d][h]
__device__ __nv_bfloat16 g_w1lo[(size_t)E_ * D_ * H_];
__device__ __nv_bfloat16 g_w2hi[(size_t)E_ * H_ * F_];   // down^T [e][h][f]
__device__ __nv_bfloat16 g_w2lo[(size_t)E_ * H_ * F_];
__device__ __nv_bfloat16 g_gwhi[(size_t)E_ * T_ * F_];   // gatedw hi [e][t][f]
__device__ __nv_bfloat16 g_gwlo[(size_t)E_ * T_ * F_];

// ---- helpers ----
__device__ __forceinline__ void split2(float v, __nv_bfloat16& h, __nv_bfloat16& l) {
    h = __float2bfloat16(v);
    l = __float2bfloat16(v - __bfloat162float(h));
}

#define CP16(dst_u32, src_ptr) \
    asm volatile("cp.async.cg.shared.global [%0], [%1], 16;" :: "r"(dst_u32), "l"(src_ptr))
#define CP_COMMIT asm volatile("cp.async.commit_group;")
#define CP_WAIT1  asm volatile("cp.async.wait_group 1;")

__device__ __forceinline__ uint32_t lds32(const char* p) { return *(const uint32_t*)p; }

__device__ __forceinline__ void mma16816(float* acc, uint32_t a0, uint32_t a1,
                                         uint32_t a2, uint32_t a3,
                                         uint32_t b0, uint32_t b1) {
    asm volatile(
        "mma.sync.aligned.m16n8k16.row.col.f32.bf16.bf16.f32 "
        "{%0,%1,%2,%3}, {%4,%5,%6,%7}, {%8,%9}, {%0,%1,%2,%3};"
        : "+f"(acc[0]), "+f"(acc[1]), "+f"(acc[2]), "+f"(acc[3])
        : "r"(a0), "r"(a1), "r"(a2), "r"(a3), "r"(b0), "r"(b1));
}

// smem stage layout (bytes): Ahi 0, Alo 12288, Bhi 24576, Blo 36864; stage stride 49152
// rows padded: 32 bf16 data + 16 pad = 48 bf16 = 96 B
#define STG_ 49152

// 3-term split mma over one k32 chunk (2 k16 steps), warp tile 64x64
__device__ __forceinline__ void compute_chunk(const char* st, float acc[4][8][4],
                                              int wr, int wc, int g, int q) {
    const char* A_hi = st;
    const char* A_lo = st + 12288;
    const char* B_hi = st + 24576;
    const char* B_lo = st + 36864;
    int arow[4], brow[8];
#pragma unroll
    for (int mi = 0; mi < 4; mi++) arow[mi] = (wr * 64 + mi * 16 + g) * 96;
#pragma unroll
    for (int ni = 0; ni < 8; ni++) brow[ni] = (wc * 64 + ni * 8 + g) * 96;
#pragma unroll
    for (int ks = 0; ks < 2; ks++) {
        int kb = ks * 32 + q * 4;
        uint32_t A[4][4];
#pragma unroll
        for (int mi = 0; mi < 4; mi++) {
            A[mi][0] = lds32(A_hi + arow[mi] + kb);
            A[mi][1] = lds32(A_hi + arow[mi] + 768 + kb);
            A[mi][2] = lds32(A_hi + arow[mi] + kb + 16);
            A[mi][3] = lds32(A_hi + arow[mi] + 768 + kb + 16);
        }
#pragma unroll
        for (int ni = 0; ni < 8; ni++) {     // ah * bh
            uint32_t b0 = lds32(B_hi + brow[ni] + kb);
            uint32_t b1 = lds32(B_hi + brow[ni] + kb + 16);
#pragma unroll
            for (int mi = 0; mi < 4; mi++)
                mma16816(acc[mi][ni], A[mi][0], A[mi][1], A[mi][2], A[mi][3], b0, b1);
        }
#pragma unroll
        for (int ni = 0; ni < 8; ni++) {     // ah * bl
            uint32_t b0 = lds32(B_lo + brow[ni] + kb);
            uint32_t b1 = lds32(B_lo + brow[ni] + kb + 16);
#pragma unroll
            for (int mi = 0; mi < 4; mi++)
                mma16816(acc[mi][ni], A[mi][0], A[mi][1], A[mi][2], A[mi][3], b0, b1);
        }
#pragma unroll
        for (int mi = 0; mi < 4; mi++) {
            A[mi][0] = lds32(A_lo + arow[mi] + kb);
            A[mi][1] = lds32(A_lo + arow[mi] + 768 + kb);
            A[mi][2] = lds32(A_lo + arow[mi] + kb + 16);
            A[mi][3] = lds32(A_lo + arow[mi] + 768 + kb + 16);
        }
#pragma unroll
        for (int ni = 0; ni < 8; ni++) {     // al * bh
            uint32_t b0 = lds32(B_hi + brow[ni] + kb);
            uint32_t b1 = lds32(B_hi + brow[ni] + kb + 16);
#pragma unroll
            for (int mi = 0; mi < 4; mi++)
                mma16816(acc[mi][ni], A[mi][0], A[mi][1], A[mi][2], A[mi][3], b0, b1);
        }
    }
}

// ===========================================================================
// K0: routing weights
// ===========================================================================
__global__ void k_route(const float* __restrict__ rw, const int* __restrict__ idx) {
    int t = blockIdx.x * blockDim.x + threadIdx.x;
    if (t >= T_) return;
    float acc[E_];
#pragma unroll
    for (int j = 0; j < E_; j++) acc[j] = 0.0f;
    for (int k = 0; k < TOPK_; k++) {
        int e = idx[t * TOPK_ + k];
        float v = rw[t * TOPK_ + k];
#pragma unroll
        for (int j = 0; j < E_; j++)
            if (j == e) acc[j] += v;
    }
#pragma unroll
    for (int j = 0; j < E_; j++) g_w[j * T_ + t] = acc[j];
}

// ===========================================================================
// split X -> hi/lo bf16
// ===========================================================================
__global__ void k_split_x(const float* __restrict__ X) {
    int i = blockIdx.x * blockDim.x + threadIdx.x;  // one float4
    float4 v = ((const float4*)X)[i];
    __nv_bfloat16 h0, l0, h1, l1, h2, l2, h3, l3;
    split2(v.x, h0, l0); split2(v.y, h1, l1);
    split2(v.z, h2, l2); split2(v.w, h3, l3);
    __nv_bfloat162* ph = (__nv_bfloat162*)g_xhi;
    __nv_bfloat162* pl = (__nv_bfloat162*)g_xlo;
    ph[i * 2]     = __nv_bfloat162(h0, h1);
    ph[i * 2 + 1] = __nv_bfloat162(h2, h3);
    pl[i * 2]     = __nv_bfloat162(l0, l1);
    pl[i * 2 + 1] = __nv_bfloat162(l2, l3);
}

// ===========================================================================
// split + transpose weights: src [E][RR][CC] fp32 -> dst [E][CC][RR] bf16 hi/lo
// grid (CC/32, RR/32, E), 256 threads (32x8)
// ===========================================================================
__global__ void k_splitT(const float* __restrict__ src, __nv_bfloat16* __restrict__ dhi,
                         __nv_bfloat16* __restrict__ dlo, int RR, int CC) {
    __shared__ __nv_bfloat16 hs[32][36], ls[32][36];
    int e = blockIdx.z;
    int c0 = blockIdx.x * 32, r0 = blockIdx.y * 32;
    int tx = threadIdx.x & 31, ty = threadIdx.x >> 5;
    const float* s = src + (size_t)e * RR * CC;
#pragma unroll
    for (int j = 0; j < 4; j++) {
        float v = s[(size_t)(r0 + ty + 8 * j) * CC + c0 + tx];
        __nv_bfloat16 h, l; split2(v, h, l);
        hs[ty + 8 * j][tx] = h; ls[ty + 8 * j][tx] = l;
    }
    __syncthreads();
    size_t dbase = (size_t)e * RR * CC;
#pragma unroll
    for (int j = 0; j < 4; j++) {
        int cc = c0 + ty + 8 * j;
        dhi[dbase + (size_t)cc * RR + r0 + tx] = hs[tx][ty + 8 * j];
        dlo[dbase + (size_t)cc * RR + r0 + tx] = ls[tx][ty + 8 * j];
    }
}

// ===========================================================================
// K1: g_xa[e,t,r] = x[t,:] @ A1[e,:,r]
// ===========================================================================
__global__ void k_loraA1(const float* __restrict__ X, const float* __restrict__ A1) {
    int warp = (blockIdx.x * blockDim.x + threadIdx.x) >> 5;
    int lane = threadIdx.x & 31;
    if (warp >= E_ * T_) return;
    int e = warp / T_, t = warp % T_;
    const float* xrow = X + (size_t)t * H_;
    float acc[R_];
#pragma unroll
    for (int r = 0; r < R_; r++) acc[r] = 0.0f;
    for (int h0 = lane * 4; h0 < H_; h0 += 128) {
        float4 xv = *(const float4*)(xrow + h0);
        const float* a = A1 + ((size_t)e * H_ + h0) * R_;
        float xs[4] = {xv.x, xv.y, xv.z, xv.w};
#pragma unroll
        for (int qd = 0; qd < 4; qd++) {
            float4 a0 = *(const float4*)(a + qd * R_);
            float4 a1 = *(const float4*)(a + qd * R_ + 4);
            acc[0] += xs[qd] * a0.x; acc[1] += xs[qd] * a0.y;
            acc[2] += xs[qd] * a0.z; acc[3] += xs[qd] * a0.w;
            acc[4] += xs[qd] * a1.x; acc[5] += xs[qd] * a1.y;
            acc[6] += xs[qd] * a1.z; acc[7] += xs[qd] * a1.w;
        }
    }
    float keep = 0.0f;
#pragma unroll
    for (int r = 0; r < R_; r++) {
        float v = acc[r];
#pragma unroll
        for (int off = 16; off; off >>= 1) v += __shfl_xor_sync(0xffffffff, v, off);
        if (lane == r) keep = v;
    }
    if (lane < R_) g_xa[(size_t)(e * T_ + t) * R_ + lane] = keep;
}

// ===========================================================================
// K3: g_la2[e,t,r] = gatedw[e,t,:] @ A2[e,:,r]   (gatedw = hi + lo)
// ===========================================================================
__global__ void k_loraA2(const float* __restrict__ A2) {
    int warp = (blockIdx.x * blockDim.x + threadIdx.x) >> 5;
    int lane = threadIdx.x & 31;
    if (warp >= E_ * T_) return;
    int e = warp / T_, t = warp % T_;
    const __nv_bfloat16* ph = g_gwhi + (size_t)(e * T_ + t) * F_;
    const __nv_bfloat16* pl = g_gwlo + (size_t)(e * T_ + t) * F_;
    float acc[R_];
#pragma unroll
    for (int r = 0; r < R_; r++) acc[r] = 0.0f;
    for (int f0 = lane * 4; f0 < F_; f0 += 128) {
        __nv_bfloat162 h0 = *(const __nv_bfloat162*)(ph + f0);
        __nv_bfloat162 h1 = *(const __nv_bfloat162*)(ph + f0 + 2);
        __nv_bfloat162 l0 = *(const __nv_bfloat162*)(pl + f0);
        __nv_bfloat162 l1 = *(const __nv_bfloat162*)(pl + f0 + 2);
        float xs[4] = {
            __bfloat162float(h0.x) + __bfloat162float(l0.x),
            __bfloat162float(h0.y) + __bfloat162float(l0.y),
            __bfloat162float(h1.x) + __bfloat162float(l1.x),
            __bfloat162float(h1.y) + __bfloat162float(l1.y)};
        const float* a = A2 + ((size_t)e * F_ + f0) * R_;
#pragma unroll
        for (int qd = 0; qd < 4; qd++) {
            float4 a0 = *(const float4*)(a + qd * R_);
            float4 a1 = *(const float4*)(a + qd * R_ + 4);
            acc[0] += xs[qd] * a0.x; acc[1] += xs[qd] * a0.y;
            acc[2] += xs[qd] * a0.z; acc[3] += xs[qd] * a0.w;
            acc[4] += xs[qd] * a1.x; acc[5] += xs[qd] * a1.y;
            acc[6] += xs[qd] * a1.z; acc[7] += xs[qd] * a1.w;
        }
    }
    float keep = 0.0f;
#pragma unroll
    for (int r = 0; r < R_; r++) {
        float v = acc[r];
#pragma unroll
        for (int off = 16; off; off >>= 1) v += __shfl_xor_sync(0xffffffff, v, off);
        if (lane == r) keep = v;
    }
    if (lane < R_) g_la2[(size_t)(e * T_ + t) * R_ + lane] = keep;
}

// ===========================================================================
// K2: HMMA GEMM1 + LoRA/bias/GLU/w epilogue -> gatedw hi/lo
// grid (D/128, T/128, E), 128 threads
// ===========================================================================
__global__ void __launch_bounds__(128, 2)
k_gemm1(const float* __restrict__ bias, const float* __restrict__ B1) {
    extern __shared__ char smem[];
    uint32_t sb = (uint32_t)__cvta_generic_to_shared(smem);
    int tid = threadIdx.x;
    int wid = tid >> 5, lane = tid & 31;
    int wr = wid >> 1, wc = wid & 1, g = lane >> 2, q = lane & 3;
    int e = blockIdx.z, m0 = blockIdx.y * 128, n0 = blockIdx.x * 128;

    float acc[4][8][4];
#pragma unroll
    for (int a = 0; a < 4; a++)
#pragma unroll
        for (int b = 0; b < 8; b++)
#pragma unroll
            for (int c = 0; c < 4; c++) acc[a][b][c] = 0.0f;

    auto issue = [&](int c, int stage) {
        int k0 = c * 32;
        uint32_t a_hi = sb + stage * STG_ + tid * 96;
        const __nv_bfloat16* sxh = g_xhi + (size_t)(m0 + tid) * H_ + k0;
        const __nv_bfloat16* sxl = g_xlo + (size_t)(m0 + tid) * H_ + k0;
        const __nv_bfloat16* swh = g_w1hi + ((size_t)e * D_ + n0 + tid) * H_ + k0;
        const __nv_bfloat16* swl = g_w1lo + ((size_t)e * D_ + n0 + tid) * H_ + k0;
#pragma unroll
        for (int j = 0; j < 4; j++) {
            CP16(a_hi + j * 16,         sxh + j * 8);
            CP16(a_hi + 12288 + j * 16, sxl + j * 8);
            CP16(a_hi + 24576 + j * 16, swh + j * 8);
            CP16(a_hi + 36864 + j * 16, swl + j * 8);
        }
    };
    issue(0, 0); CP_COMMIT;
    issue(1, 1); CP_COMMIT;
    const int NCH = H_ / 32;
    for (int c = 0; c < NCH; c++) {
        CP_WAIT1;
        __syncthreads();
        compute_chunk(smem + (c & 1) * STG_, acc, wr, wc, g, q);
        __syncthreads();
        if (c + 2 < NCH) issue(c + 2, c & 1);
        CP_COMMIT;
    }

    // ---- epilogue ----
    float* xa_s   = (float*)smem;            // [128][8]
    float* b1_s   = (float*)(smem + 4096);   // [8][128]
    float* bias_s = (float*)(smem + 8192);   // [128]
    float* w_s    = (float*)(smem + 8704);   // [128]
    for (int i = tid; i < 1024; i += 128) {
        xa_s[i] = g_xa[((size_t)e * T_ + m0 + (i >> 3)) * 8 + (i & 7)] * SCALING_;
        b1_s[i] = B1[((size_t)e * 8 + (i >> 7)) * D_ + n0 + (i & 127)];
    }
    bias_s[tid] = bias[(size_t)e * D_ + n0 + tid];
    w_s[tid] = g_w[e * T_ + m0 + tid];
    __syncthreads();

#pragma unroll
    for (int mi = 0; mi < 4; mi++) {
#pragma unroll
        for (int ni = 0; ni < 8; ni++) {
            int c = wc * 64 + ni * 8 + q * 2;
            float2 bia = *(const float2*)&bias_s[c];
#pragma unroll
            for (int h = 0; h < 2; h++) {
                int row = wr * 64 + mi * 16 + g + h * 8;
                float gate = acc[mi][ni][h * 2 + 0] + bia.x;
                float up   = acc[mi][ni][h * 2 + 1] + bia.y;
                const float* xr = &xa_s[row * 8];
#pragma unroll
                for (int p = 0; p < 8; p++) {
                    float2 b1v = *(const float2*)&b1_s[p * 128 + c];
                    gate += xr[p] * b1v.x;
                    up   += xr[p] * b1v.y;
                }
                gate = fminf(gate, LIMIT_);
                up = fminf(fmaxf(up, -LIMIT_), LIMIT_);
                float glu = gate / (1.0f + expf(-ACT_ALPHA_ * gate));
                float val = w_s[row] * (up + 1.0f) * glu;
                __nv_bfloat16 hh, ll; split2(val, hh, ll);
                size_t oidx = ((size_t)e * T_ + m0 + row) * F_ + ((n0 + c) >> 1);
                g_gwhi[oidx] = hh; g_gwlo[oidx] = ll;
            }
        }
    }
}

// ===========================================================================
// K4: HMMA GEMM2 over all experts + LoRA/bias epilogue -> out
// grid (H/128, T/128), 128 threads
// ===========================================================================
__global__ void __launch_bounds__(128, 2)
k_gemm2(const float* __restrict__ bias2, const float* __restrict__ B2,
        float* __restrict__ out) {
    extern __shared__ char smem[];
    uint32_t sb = (uint32_t)__cvta_generic_to_shared(smem);
    int tid = threadIdx.x;
    int wid = tid >> 5, lane = tid & 31;
    int wr = wid >> 1, wc = wid & 1, g = lane >> 2, q = lane & 3;
    int m0 = blockIdx.y * 128, n0 = blockIdx.x * 128;

    float acc[4][8][4];
#pragma unroll
    for (int a = 0; a < 4; a++)
#pragma unroll
        for (int b = 0; b < 8; b++)
#pragma unroll
            for (int c = 0; c < 4; c++) acc[a][b][c] = 0.0f;

    auto issue = [&](int c, int stage) {
        int ee = c >> 5, f0 = (c & 31) * 32;
        uint32_t a_hi = sb + stage * STG_ + tid * 96;
        const __nv_bfloat16* sah = g_gwhi + ((size_t)ee * T_ + m0 + tid) * F_ + f0;
        const __nv_bfloat16* sal = g_gwlo + ((size_t)ee * T_ + m0 + tid) * F_ + f0;
        const __nv_bfloat16* sbh = g_w2hi + ((size_t)ee * H_ + n0 + tid) * F_ + f0;
        const __nv_bfloat16* sbl = g_w2lo + ((size_t)ee * H_ + n0 + tid) * F_ + f0;
#pragma unroll
        for (int j = 0; j < 4; j++) {
            CP16(a_hi + j * 16,         sah + j * 8);
            CP16(a_hi + 12288 + j * 16, sal + j * 8);
            CP16(a_hi + 24576 + j * 16, sbh + j * 8);
            CP16(a_hi + 36864 + j * 16, sbl + j * 8);
        }
    };
    issue(0, 0); CP_COMMIT;
    issue(1, 1); CP_COMMIT;
    const int NCH = E_ * F_ / 32;
    for (int c = 0; c < NCH; c++) {
        CP_WAIT1;
        __syncthreads();
        compute_chunk(smem + (c & 1) * STG_, acc, wr, wc, g, q);
        __syncthreads();
        if (c + 2 < NCH) issue(c + 2, c & 1);
        CP_COMMIT;
    }

    // ---- epilogue ----
    float* la_s = (float*)smem;            // [128][64]  (e*8+r)
    float* b2_s = (float*)(smem + 32768);  // [64][128]
    float* wv_s = (float*)(smem + 65536);  // [128][8]
    float* bb_s = (float*)(smem + 69632);  // [8][128]
    for (int i = tid; i < 8192; i += 128) {
        int r = i >> 6, j = i & 63;
        la_s[i] = g_la2[((size_t)(j >> 3) * T_ + m0 + r) * 8 + (j & 7)] * SCALING_;
        b2_s[i] = B2[(size_t)(i >> 7) * H_ + n0 + (i & 127)];
    }
    for (int i = tid; i < 1024; i += 128) {
        wv_s[i] = g_w[(i & 7) * T_ + m0 + (i >> 3)];
        bb_s[i] = bias2[(size_t)(i >> 7) * H_ + n0 + (i & 127)];
    }
    __syncthreads();

#pragma unroll
    for (int mi = 0; mi < 4; mi++) {
#pragma unroll
        for (int ni = 0; ni < 8; ni++) {
            int c = wc * 64 + ni * 8 + q * 2;
#pragma unroll
            for (int h = 0; h < 2; h++) {
                int row = wr * 64 + mi * 16 + g + h * 8;
                float v0 = acc[mi][ni][h * 2 + 0];
                float v1 = acc[mi][ni][h * 2 + 1];
                const float* la = &la_s[row * 64];
#pragma unroll 8
                for (int j = 0; j < 64; j++) {
                    float2 bv = *(const float2*)&b2_s[j * 128 + c];
                    v0 += la[j] * bv.x;
                    v1 += la[j] * bv.y;
                }
                const float* wr8 = &wv_s[row * 8];
#pragma unroll
                for (int ee = 0; ee < 8; ee++) {
                    float2 bv = *(const float2*)&bb_s[ee * 128 + c];
                    v0 += wr8[ee] * bv.x;
                    v1 += wr8[ee] * bv.y;
                }
                *(float2*)(out + (size_t)(m0 + row) * H_ + n0 + c) = make_float2(v0, v1);
            }
        }
    }
}

// ===========================================================================
extern "C" void kernel_launch(void* const* d_in, const int* in_sizes, int n_in,
                              void* d_out, int out_size) {
    const float* x      = (const float*)d_in[0];
    const float* rw     = (const float*)d_in[1];
    const float* gup    = (const float*)d_in[2];
    const float* gup_b  = (const float*)d_in[3];
    const float* dn     = (const float*)d_in[4];
    const float* dn_b   = (const float*)d_in[5];
    const float* A1     = (const float*)d_in[6];
    const float* B1     = (const float*)d_in[7];
    const float* A2     = (const float*)d_in[8];
    const float* B2     = (const float*)d_in[9];
    const int*   ri     = (const int*)d_in[10];   // int32 (JAX x64 off)
    float* out = (float*)d_out;

    static bool attr_done = false;
    if (!attr_done) {
        cudaFuncSetAttribute(k_gemm1, cudaFuncAttributeMaxDynamicSharedMemorySize, 2 * STG_);
        cudaFuncSetAttribute(k_gemm2, cudaFuncAttributeMaxDynamicSharedMemorySize, 2 * STG_);
        attr_done = true;
    }

    __nv_bfloat16 *w1hi, *w1lo, *w2hi, *w2lo;
    cudaGetSymbolAddress((void**)&w1hi, g_w1hi);
    cudaGetSymbolAddress((void**)&w1lo, g_w1lo);
    cudaGetSymbolAddress((void**)&w2hi, g_w2hi);
    cudaGetSymbolAddress((void**)&w2lo, g_w2lo);

    k_route<<<(T_ + 127) / 128, 128>>>(rw, ri);
    k_split_x<<<(T_ * H_ / 4) / 256, 256>>>(x);
    k_splitT<<<dim3(D_ / 32, H_ / 32, E_), 256>>>(gup, w1hi, w1lo, H_, D_);
    k_splitT<<<dim3(H_ / 32, F_ / 32, E_), 256>>>(dn, w2hi, w2lo, F_, H_);
    k_loraA1<<<(E_ * T_) / 8, 256>>>(x, A1);
    k_gemm1<<<dim3(D_ / 128, T_ / 128, E_), 128, 2 * STG_>>>(gup_b, B1);
    k_loraA2<<<(E_ * T_) / 8, 256>>>(A2);
    k_gemm2<<<dim3(H_ / 128, T_ / 128), 128, 2 * STG_>>>(dn_b, B2, out);
}

// round 5
// speedup vs baseline: 4.2627x; 2.1956x over previous
#include <cuda_runtime.h>
#include <cuda_bf16.h>
#include <cstdint>
#include <math.h>

#define E_ 8
#define H_ 2048
#define F_ 1024
#define D_ 2048
#define T_ 2048
#define TOPK_ 4
#define R_ 8
#define SCALING_ 2.0f
#define LIMIT_ 7.0f
#define ACT_ALPHA_ 1.702f

// ---- scratch (__device__ globals; allocation-free per harness rules) ----
__device__ float g_w[E_ * T_];                 // routing weight per (e,t)
__device__ int   g_cnt[E_];                    // active tokens per expert
__device__ int   g_list[E_ * T_];              // [e][slot] -> token
__device__ int   g_slot[E_ * T_];              // [e][t] -> slot or -1
__device__ float g_xa[E_ * T_ * R_];           // compacted [e][slot][r]
__device__ float g_la2[E_ * T_ * R_];          // compacted [e][slot][r]
__device__ __nv_bfloat16 g_xhi[(size_t)T_ * H_];
__device__ __nv_bfloat16 g_xlo[(size_t)T_ * H_];
__device__ __nv_bfloat16 g_w1hi[(size_t)E_ * D_ * H_];   // gate_up^T [e][d][h]
__device__ __nv_bfloat16 g_w1lo[(size_t)E_ * D_ * H_];
__device__ __nv_bfloat16 g_w2hi[(size_t)E_ * H_ * F_];   // down^T [e][h][f]
__device__ __nv_bfloat16 g_w2lo[(size_t)E_ * H_ * F_];
__device__ __nv_bfloat16 g_gwhi[(size_t)E_ * T_ * F_];   // compacted gatedw hi
__device__ __nv_bfloat16 g_gwlo[(size_t)E_ * T_ * F_];
__device__ float g_outc[(size_t)E_ * T_ * H_];           // per-expert contributions

// ---- helpers ----
__device__ __forceinline__ void split2(float v, __nv_bfloat16& h, __nv_bfloat16& l) {
    h = __float2bfloat16(v);
    l = __float2bfloat16(v - __bfloat162float(h));
}

#define CP16(dst_u32, src_ptr) \
    asm volatile("cp.async.cg.shared.global [%0], [%1], 16;" :: "r"(dst_u32), "l"(src_ptr))
#define CP_COMMIT asm volatile("cp.async.commit_group;")
#define CP_WAIT1  asm volatile("cp.async.wait_group 1;")

__device__ __forceinline__ uint32_t lds32(const char* p) { return *(const uint32_t*)p; }

__device__ __forceinline__ void mma16816(float* acc, uint32_t a0, uint32_t a1,
                                         uint32_t a2, uint32_t a3,
                                         uint32_t b0, uint32_t b1) {
    asm volatile(
        "mma.sync.aligned.m16n8k16.row.col.f32.bf16.bf16.f32 "
        "{%0,%1,%2,%3}, {%4,%5,%6,%7}, {%8,%9}, {%0,%1,%2,%3};"
        : "+f"(acc[0]), "+f"(acc[1]), "+f"(acc[2]), "+f"(acc[3])
        : "r"(a0), "r"(a1), "r"(a2), "r"(a3), "r"(b0), "r"(b1));
}

// smem stage layout (bytes): Ahi 0, Alo 12288, Bhi 24576, Blo 36864; stage stride 49152
// rows: 32 bf16 data + 16 pad = 96 B
#define STG_ 49152

// 3-term split mma over one k32 chunk (2 k16 steps), warp tile 64x64
__device__ __forceinline__ void compute_chunk(const char* st, float acc[4][8][4],
                                              int wr, int wc, int g, int q) {
    const char* A_hi = st;
    const char* A_lo = st + 12288;
    const char* B_hi = st + 24576;
    const char* B_lo = st + 36864;
    int arow[4], brow[8];
#pragma unroll
    for (int mi = 0; mi < 4; mi++) arow[mi] = (wr * 64 + mi * 16 + g) * 96;
#pragma unroll
    for (int ni = 0; ni < 8; ni++) brow[ni] = (wc * 64 + ni * 8 + g) * 96;
#pragma unroll
    for (int ks = 0; ks < 2; ks++) {
        int kb = ks * 32 + q * 4;
        uint32_t A[4][4];
#pragma unroll
        for (int mi = 0; mi < 4; mi++) {
            A[mi][0] = lds32(A_hi + arow[mi] + kb);
            A[mi][1] = lds32(A_hi + arow[mi] + 768 + kb);
            A[mi][2] = lds32(A_hi + arow[mi] + kb + 16);
            A[mi][3] = lds32(A_hi + arow[mi] + 768 + kb + 16);
        }
#pragma unroll
        for (int ni = 0; ni < 8; ni++) {     // ah * bh
            uint32_t b0 = lds32(B_hi + brow[ni] + kb);
            uint32_t b1 = lds32(B_hi + brow[ni] + kb + 16);
#pragma unroll
            for (int mi = 0; mi < 4; mi++)
                mma16816(acc[mi][ni], A[mi][0], A[mi][1], A[mi][2], A[mi][3], b0, b1);
        }
#pragma unroll
        for (int ni = 0; ni < 8; ni++) {     // ah * bl
            uint32_t b0 = lds32(B_lo + brow[ni] + kb);
            uint32_t b1 = lds32(B_lo + brow[ni] + kb + 16);
#pragma unroll
            for (int mi = 0; mi < 4; mi++)
                mma16816(acc[mi][ni], A[mi][0], A[mi][1], A[mi][2], A[mi][3], b0, b1);
        }
#pragma unroll
        for (int mi = 0; mi < 4; mi++) {
            A[mi][0] = lds32(A_lo + arow[mi] + kb);
            A[mi][1] = lds32(A_lo + arow[mi] + 768 + kb);
            A[mi][2] = lds32(A_lo + arow[mi] + kb + 16);
            A[mi][3] = lds32(A_lo + arow[mi] + 768 + kb + 16);
        }
#pragma unroll
        for (int ni = 0; ni < 8; ni++) {     // al * bh
            uint32_t b0 = lds32(B_hi + brow[ni] + kb);
            uint32_t b1 = lds32(B_hi + brow[ni] + kb + 16);
#pragma unroll
            for (int mi = 0; mi < 4; mi++)
                mma16816(acc[mi][ni], A[mi][0], A[mi][1], A[mi][2], A[mi][3], b0, b1);
        }
    }
}

// ===========================================================================
// zero counters (graph replays need re-init every launch)
// ===========================================================================
__global__ void k_zero() {
    if (threadIdx.x < E_) g_cnt[threadIdx.x] = 0;
}

// ===========================================================================
// K0: routing weights + per-expert compacted token lists
// ===========================================================================
__global__ void k_route(const float* __restrict__ rw, const int* __restrict__ idx) {
    int t = blockIdx.x * blockDim.x + threadIdx.x;
    if (t >= T_) return;
    float acc[E_];
    int act[E_];
#pragma unroll
    for (int j = 0; j < E_; j++) { acc[j] = 0.0f; act[j] = 0; }
    for (int k = 0; k < TOPK_; k++) {
        int e = idx[t * TOPK_ + k];
        float v = rw[t * TOPK_ + k];
#pragma unroll
        for (int j = 0; j < E_; j++)
            if (j == e) { acc[j] += v; act[j] = 1; }
    }
#pragma unroll
    for (int j = 0; j < E_; j++) {
        g_w[j * T_ + t] = acc[j];
        int s = -1;
        if (act[j]) {
            s = atomicAdd(&g_cnt[j], 1);
            g_list[j * T_ + s] = t;
        }
        g_slot[j * T_ + t] = s;
    }
}

// ===========================================================================
// split X -> hi/lo bf16
// ===========================================================================
__global__ void k_split_x(const float* __restrict__ X) {
    int i = blockIdx.x * blockDim.x + threadIdx.x;  // one float4
    float4 v = ((const float4*)X)[i];
    __nv_bfloat16 h0, l0, h1, l1, h2, l2, h3, l3;
    split2(v.x, h0, l0); split2(v.y, h1, l1);
    split2(v.z, h2, l2); split2(v.w, h3, l3);
    __nv_bfloat162* ph = (__nv_bfloat162*)g_xhi;
    __nv_bfloat162* pl = (__nv_bfloat162*)g_xlo;
    ph[i * 2]     = __nv_bfloat162(h0, h1);
    ph[i * 2 + 1] = __nv_bfloat162(h2, h3);
    pl[i * 2]     = __nv_bfloat162(l0, l1);
    pl[i * 2 + 1] = __nv_bfloat162(l2, l3);
}

// ===========================================================================
// split + transpose weights: src [E][RR][CC] fp32 -> dst [E][CC][RR] bf16 hi/lo
// ===========================================================================
__global__ void k_splitT(const float* __restrict__ src, __nv_bfloat16* __restrict__ dhi,
                         __nv_bfloat16* __restrict__ dlo, int RR, int CC) {
    __shared__ __nv_bfloat16 hs[32][36], ls[32][36];
    int e = blockIdx.z;
    int c0 = blockIdx.x * 32, r0 = blockIdx.y * 32;
    int tx = threadIdx.x & 31, ty = threadIdx.x >> 5;
    const float* s = src + (size_t)e * RR * CC;
#pragma unroll
    for (int j = 0; j < 4; j++) {
        float v = s[(size_t)(r0 + ty + 8 * j) * CC + c0 + tx];
        __nv_bfloat16 h, l; split2(v, h, l);
        hs[ty + 8 * j][tx] = h; ls[ty + 8 * j][tx] = l;
    }
    __syncthreads();
    size_t dbase = (size_t)e * RR * CC;
#pragma unroll
    for (int j = 0; j < 4; j++) {
        int cc = c0 + ty + 8 * j;
        dhi[dbase + (size_t)cc * RR + r0 + tx] = hs[tx][ty + 8 * j];
        dlo[dbase + (size_t)cc * RR + r0 + tx] = ls[tx][ty + 8 * j];
    }
}

// ===========================================================================
// K1 (gathered): g_xa[e,slot,r] = x[tok,:] @ A1[e,:,r]
// ===========================================================================
__global__ void k_loraA1(const float* __restrict__ X, const float* __restrict__ A1) {
    int warp = (blockIdx.x * blockDim.x + threadIdx.x) >> 5;
    int lane = threadIdx.x & 31;
    int e = warp / T_, slot = warp % T_;
    if (slot >= g_cnt[e]) return;
    int t = g_list[e * T_ + slot];
    const float* xrow = X + (size_t)t * H_;
    float acc[R_];
#pragma unroll
    for (int r = 0; r < R_; r++) acc[r] = 0.0f;
    for (int h0 = lane * 4; h0 < H_; h0 += 128) {
        float4 xv = *(const float4*)(xrow + h0);
        const float* a = A1 + ((size_t)e * H_ + h0) * R_;
        float xs[4] = {xv.x, xv.y, xv.z, xv.w};
#pragma unroll
        for (int qd = 0; qd < 4; qd++) {
            float4 a0 = *(const float4*)(a + qd * R_);
            float4 a1 = *(const float4*)(a + qd * R_ + 4);
            acc[0] += xs[qd] * a0.x; acc[1] += xs[qd] * a0.y;
            acc[2] += xs[qd] * a0.z; acc[3] += xs[qd] * a0.w;
            acc[4] += xs[qd] * a1.x; acc[5] += xs[qd] * a1.y;
            acc[6] += xs[qd] * a1.z; acc[7] += xs[qd] * a1.w;
        }
    }
    float keep = 0.0f;
#pragma unroll
    for (int r = 0; r < R_; r++) {
        float v = acc[r];
#pragma unroll
        for (int off = 16; off; off >>= 1) v += __shfl_xor_sync(0xffffffff, v, off);
        if (lane == r) keep = v;
    }
    if (lane < R_) g_xa[(size_t)(e * T_ + slot) * R_ + lane] = keep;
}

// ===========================================================================
// K3 (gathered): g_la2[e,slot,r] = gatedw[e,slot,:] @ A2[e,:,r]
// ===========================================================================
__global__ void k_loraA2(const float* __restrict__ A2) {
    int warp = (blockIdx.x * blockDim.x + threadIdx.x) >> 5;
    int lane = threadIdx.x & 31;
    int e = warp / T_, slot = warp % T_;
    if (slot >= g_cnt[e]) return;
    const __nv_bfloat16* ph = g_gwhi + (size_t)(e * T_ + slot) * F_;
    const __nv_bfloat16* pl = g_gwlo + (size_t)(e * T_ + slot) * F_;
    float acc[R_];
#pragma unroll
    for (int r = 0; r < R_; r++) acc[r] = 0.0f;
    for (int f0 = lane * 4; f0 < F_; f0 += 128) {
        __nv_bfloat162 h0 = *(const __nv_bfloat162*)(ph + f0);
        __nv_bfloat162 h1 = *(const __nv_bfloat162*)(ph + f0 + 2);
        __nv_bfloat162 l0 = *(const __nv_bfloat162*)(pl + f0);
        __nv_bfloat162 l1 = *(const __nv_bfloat162*)(pl + f0 + 2);
        float xs[4] = {
            __bfloat162float(h0.x) + __bfloat162float(l0.x),
            __bfloat162float(h0.y) + __bfloat162float(l0.y),
            __bfloat162float(h1.x) + __bfloat162float(l1.x),
            __bfloat162float(h1.y) + __bfloat162float(l1.y)};
        const float* a = A2 + ((size_t)e * F_ + f0) * R_;
#pragma unroll
        for (int qd = 0; qd < 4; qd++) {
            float4 a0 = *(const float4*)(a + qd * R_);
            float4 a1 = *(const float4*)(a + qd * R_ + 4);
            acc[0] += xs[qd] * a0.x; acc[1] += xs[qd] * a0.y;
            acc[2] += xs[qd] * a0.z; acc[3] += xs[qd] * a0.w;
            acc[4] += xs[qd] * a1.x; acc[5] += xs[qd] * a1.y;
            acc[6] += xs[qd] * a1.z; acc[7] += xs[qd] * a1.w;
        }
    }
    float keep = 0.0f;
#pragma unroll
    for (int r = 0; r < R_; r++) {
        float v = acc[r];
#pragma unroll
        for (int off = 16; off; off >>= 1) v += __shfl_xor_sync(0xffffffff, v, off);
        if (lane == r) keep = v;
    }
    if (lane < R_) g_la2[(size_t)(e * T_ + slot) * R_ + lane] = keep;
}

// ===========================================================================
// K2 (gathered): HMMA GEMM1 over active tokens of expert e
// grid (D/128, 16 max m-tiles, E), 128 threads
// ===========================================================================
__global__ void __launch_bounds__(128, 2)
k_gemm1(const float* __restrict__ bias, const float* __restrict__ B1) {
    int e = blockIdx.z, m0 = blockIdx.y * 128, n0 = blockIdx.x * 128;
    int cnt = g_cnt[e];
    if (m0 >= cnt) return;
    extern __shared__ char smem[];
    uint32_t sb = (uint32_t)__cvta_generic_to_shared(smem);
    int tid = threadIdx.x;
    int wid = tid >> 5, lane = tid & 31;
    int wr = wid >> 1, wc = wid & 1, g = lane >> 2, q = lane & 3;

    int tok = g_list[e * T_ + (m0 + tid < cnt ? m0 + tid : m0)];

    float acc[4][8][4];
#pragma unroll
    for (int a = 0; a < 4; a++)
#pragma unroll
        for (int b = 0; b < 8; b++)
#pragma unroll
            for (int c = 0; c < 4; c++) acc[a][b][c] = 0.0f;

    auto issue = [&](int c, int stage) {
        int k0 = c * 32;
        uint32_t a_hi = sb + stage * STG_ + tid * 96;
        const __nv_bfloat16* sxh = g_xhi + (size_t)tok * H_ + k0;
        const __nv_bfloat16* sxl = g_xlo + (size_t)tok * H_ + k0;
        const __nv_bfloat16* swh = g_w1hi + ((size_t)e * D_ + n0 + tid) * H_ + k0;
        const __nv_bfloat16* swl = g_w1lo + ((size_t)e * D_ + n0 + tid) * H_ + k0;
#pragma unroll
        for (int j = 0; j < 4; j++) {
            CP16(a_hi + j * 16,         sxh + j * 8);
            CP16(a_hi + 12288 + j * 16, sxl + j * 8);
            CP16(a_hi + 24576 + j * 16, swh + j * 8);
            CP16(a_hi + 36864 + j * 16, swl + j * 8);
        }
    };
    issue(0, 0); CP_COMMIT;
    issue(1, 1); CP_COMMIT;
    const int NCH = H_ / 32;
    for (int c = 0; c < NCH; c++) {
        CP_WAIT1;
        __syncthreads();
        compute_chunk(smem + (c & 1) * STG_, acc, wr, wc, g, q);
        __syncthreads();
        if (c + 2 < NCH) issue(c + 2, c & 1);
        CP_COMMIT;
    }

    // ---- epilogue ----
    float* xa_s   = (float*)smem;            // [128][8]
    float* b1_s   = (float*)(smem + 4096);   // [8][128]
    float* bias_s = (float*)(smem + 8192);   // [128]
    float* w_s    = (float*)(smem + 8704);   // [128]
    for (int i = tid; i < 1024; i += 128) {
        xa_s[i] = g_xa[((size_t)e * T_ + m0 + (i >> 3)) * 8 + (i & 7)] * SCALING_;
        b1_s[i] = B1[((size_t)e * 8 + (i >> 7)) * D_ + n0 + (i & 127)];
    }
    bias_s[tid] = bias[(size_t)e * D_ + n0 + tid];
    w_s[tid] = (m0 + tid < cnt) ? g_w[e * T_ + tok] : 0.0f;
    __syncthreads();

#pragma unroll
    for (int mi = 0; mi < 4; mi++) {
#pragma unroll
        for (int ni = 0; ni < 8; ni++) {
            int c = wc * 64 + ni * 8 + q * 2;
            float2 bia = *(const float2*)&bias_s[c];
#pragma unroll
            for (int h = 0; h < 2; h++) {
                int row = wr * 64 + mi * 16 + g + h * 8;
                if (m0 + row >= cnt) continue;
                float gate = acc[mi][ni][h * 2 + 0] + bia.x;
                float up   = acc[mi][ni][h * 2 + 1] + bia.y;
                const float* xr = &xa_s[row * 8];
#pragma unroll
                for (int p = 0; p < 8; p++) {
                    float2 b1v = *(const float2*)&b1_s[p * 128 + c];
                    gate += xr[p] * b1v.x;
                    up   += xr[p] * b1v.y;
                }
                gate = fminf(gate, LIMIT_);
                up = fminf(fmaxf(up, -LIMIT_), LIMIT_);
                float glu = gate / (1.0f + expf(-ACT_ALPHA_ * gate));
                float val = w_s[row] * (up + 1.0f) * glu;
                __nv_bfloat16 hh, ll; split2(val, hh, ll);
                size_t oidx = ((size_t)e * T_ + m0 + row) * F_ + ((n0 + c) >> 1);
                g_gwhi[oidx] = hh; g_gwlo[oidx] = ll;
            }
        }
    }
}

// ===========================================================================
// K4 (gathered): per-expert HMMA GEMM2 -> g_outc[e][slot][h]
// grid (H/128, 16 max m-tiles, E), 128 threads
// ===========================================================================
__global__ void __launch_bounds__(128, 2)
k_gemm2(const float* __restrict__ bias2, const float* __restrict__ B2) {
    int e = blockIdx.z, m0 = blockIdx.y * 128, n0 = blockIdx.x * 128;
    int cnt = g_cnt[e];
    if (m0 >= cnt) return;
    extern __shared__ char smem[];
    uint32_t sb = (uint32_t)__cvta_generic_to_shared(smem);
    int tid = threadIdx.x;
    int wid = tid >> 5, lane = tid & 31;
    int wr = wid >> 1, wc = wid & 1, g = lane >> 2, q = lane & 3;

    float acc[4][8][4];
#pragma unroll
    for (int a = 0; a < 4; a++)
#pragma unroll
        for (int b = 0; b < 8; b++)
#pragma unroll
            for (int c = 0; c < 4; c++) acc[a][b][c] = 0.0f;

    auto issue = [&](int c, int stage) {
        int f0 = c * 32;
        uint32_t a_hi = sb + stage * STG_ + tid * 96;
        const __nv_bfloat16* sah = g_gwhi + ((size_t)e * T_ + m0 + tid) * F_ + f0;
        const __nv_bfloat16* sal = g_gwlo + ((size_t)e * T_ + m0 + tid) * F_ + f0;
        const __nv_bfloat16* sbh = g_w2hi + ((size_t)e * H_ + n0 + tid) * F_ + f0;
        const __nv_bfloat16* sbl = g_w2lo + ((size_t)e * H_ + n0 + tid) * F_ + f0;
#pragma unroll
        for (int j = 0; j < 4; j++) {
            CP16(a_hi + j * 16,         sah + j * 8);
            CP16(a_hi + 12288 + j * 16, sal + j * 8);
            CP16(a_hi + 24576 + j * 16, sbh + j * 8);
            CP16(a_hi + 36864 + j * 16, sbl + j * 8);
        }
    };
    issue(0, 0); CP_COMMIT;
    issue(1, 1); CP_COMMIT;
    const int NCH = F_ / 32;
    for (int c = 0; c < NCH; c++) {
        CP_WAIT1;
        __syncthreads();
        compute_chunk(smem + (c & 1) * STG_, acc, wr, wc, g, q);
        __syncthreads();
        if (c + 2 < NCH) issue(c + 2, c & 1);
        CP_COMMIT;
    }

    // ---- epilogue: += SCALING*la2@B2 + w*bias2; store to outc ----
    float* la_s = (float*)smem;            // [128][8]
    float* b2_s = (float*)(smem + 4096);   // [8][128]
    float* bb_s = (float*)(smem + 8192);   // [128]
    float* w_s  = (float*)(smem + 8704);   // [128]
    for (int i = tid; i < 1024; i += 128) {
        la_s[i] = g_la2[((size_t)e * T_ + m0 + (i >> 3)) * 8 + (i & 7)] * SCALING_;
        b2_s[i] = B2[((size_t)e * 8 + (i >> 7)) * H_ + n0 + (i & 127)];
    }
    bb_s[tid] = bias2[(size_t)e * H_ + n0 + tid];
    {
        int gs = m0 + tid;
        w_s[tid] = (gs < cnt) ? g_w[e * T_ + g_list[e * T_ + gs]] : 0.0f;
    }
    __syncthreads();

#pragma unroll
    for (int mi = 0; mi < 4; mi++) {
#pragma unroll
        for (int ni = 0; ni < 8; ni++) {
            int c = wc * 64 + ni * 8 + q * 2;
            float2 bb = *(const float2*)&bb_s[c];
#pragma unroll
            for (int h = 0; h < 2; h++) {
                int row = wr * 64 + mi * 16 + g + h * 8;
                if (m0 + row >= cnt) continue;
                float v0 = acc[mi][ni][h * 2 + 0];
                float v1 = acc[mi][ni][h * 2 + 1];
                const float* la = &la_s[row * 8];
#pragma unroll
                for (int p = 0; p < 8; p++) {
                    float2 bv = *(const float2*)&b2_s[p * 128 + c];
                    v0 += la[p] * bv.x;
                    v1 += la[p] * bv.y;
                }
                float wt = w_s[row];
                v0 += wt * bb.x;
                v1 += wt * bb.y;
                *(float2*)(g_outc + ((size_t)e * T_ + m0 + row) * H_ + n0 + c) =
                    make_float2(v0, v1);
            }
        }
    }
}

// ===========================================================================
// K5: combine per-expert contributions -> out
// block per token, 128 threads; thread j handles h = j*4 + k*512, k=0..3
// ===========================================================================
__global__ void __launch_bounds__(128)
k_combine(float* __restrict__ out) {
    int t = blockIdx.x;
    int tid = threadIdx.x;
    int slots[E_];
#pragma unroll
    for (int e = 0; e < E_; e++) slots[e] = g_slot[e * T_ + t];
#pragma unroll
    for (int k = 0; k < 4; k++) {
        int h = tid * 4 + k * 512;
        float4 acc = make_float4(0.f, 0.f, 0.f, 0.f);
#pragma unroll
        for (int e = 0; e < E_; e++) {
            int s = slots[e];
            if (s >= 0) {
                float4 v = *(const float4*)(g_outc + ((size_t)e * T_ + s) * H_ + h);
                acc.x += v.x; acc.y += v.y; acc.z += v.z; acc.w += v.w;
            }
        }
        *(float4*)(out + (size_t)t * H_ + h) = acc;
    }
}

// ===========================================================================
extern "C" void kernel_launch(void* const* d_in, const int* in_sizes, int n_in,
                              void* d_out, int out_size) {
    const float* x      = (const float*)d_in[0];
    const float* rw     = (const float*)d_in[1];
    const float* gup    = (const float*)d_in[2];
    const float* gup_b  = (const float*)d_in[3];
    const float* dn     = (const float*)d_in[4];
    const float* dn_b   = (const float*)d_in[5];
    const float* A1     = (const float*)d_in[6];
    const float* B1     = (const float*)d_in[7];
    const float* A2     = (const float*)d_in[8];
    const float* B2     = (const float*)d_in[9];
    const int*   ri     = (const int*)d_in[10];   // int32 (JAX x64 off)
    float* out = (float*)d_out;

    static bool attr_done = false;
    if (!attr_done) {
        cudaFuncSetAttribute(k_gemm1, cudaFuncAttributeMaxDynamicSharedMemorySize, 2 * STG_);
        cudaFuncSetAttribute(k_gemm2, cudaFuncAttributeMaxDynamicSharedMemorySize, 2 * STG_);
        attr_done = true;
    }

    __nv_bfloat16 *w1hi, *w1lo, *w2hi, *w2lo;
    cudaGetSymbolAddress((void**)&w1hi, g_w1hi);
    cudaGetSymbolAddress((void**)&w1lo, g_w1lo);
    cudaGetSymbolAddress((void**)&w2hi, g_w2hi);
    cudaGetSymbolAddress((void**)&w2lo, g_w2lo);

    k_zero<<<1, 32>>>();
    k_route<<<(T_ + 127) / 128, 128>>>(rw, ri);
    k_split_x<<<(T_ * H_ / 4) / 256, 256>>>(x);
    k_splitT<<<dim3(D_ / 32, H_ / 32, E_), 256>>>(gup, w1hi, w1lo, H_, D_);
    k_splitT<<<dim3(H_ / 32, F_ / 32, E_), 256>>>(dn, w2hi, w2lo, F_, H_);
    k_loraA1<<<(E_ * T_) / 8, 256>>>(x, A1);
    k_gemm1<<<dim3(D_ / 128, T_ / 128, E_), 128, 2 * STG_>>>(gup_b, B1);
    k_loraA2<<<(E_ * T_) / 8, 256>>>(A2);
    k_gemm2<<<dim3(H_ / 128, T_ / 128, E_), 128, 2 * STG_>>>(dn_b, B2);
    k_combine<<<T_, 128>>>(out);
}

// round 6
// speedup vs baseline: 5.5451x; 1.3008x over previous
#include <cuda_runtime.h>
#include <cuda_fp16.h>
#include <cstdint>
#include <math.h>

#define E_ 8
#define H_ 2048
#define F_ 1024
#define D_ 2048
#define T_ 2048
#define TOPK_ 4
#define R_ 8
#define SCALING_ 2.0f
#define LIMIT_ 7.0f
#define ACT_ALPHA_ 1.702f

// ---- scratch (__device__ globals; allocation-free per harness rules) ----
__device__ float g_w[E_ * T_];                 // routing weight per (e,t)
__device__ int   g_cnt[E_];                    // active tokens per expert
__device__ int   g_list[E_ * T_];              // [e][slot] -> token
__device__ int   g_slot[E_ * T_];              // [e][t] -> slot or -1
__device__ float g_xa[E_ * T_ * R_];           // compacted [e][slot][r]
__device__ float g_la2[E_ * T_ * R_];          // compacted [e][slot][r]
__device__ __half g_xhi[(size_t)T_ * H_];
__device__ __half g_xlo[(size_t)T_ * H_];
__device__ __half g_w1h[(size_t)E_ * D_ * H_];   // gate_up^T [e][d][h], fp16
__device__ __half g_w2h[(size_t)E_ * H_ * F_];   // down^T [e][h][f], fp16
__device__ __half g_gwhi[(size_t)E_ * T_ * F_];  // compacted gatedw hi
__device__ __half g_gwlo[(size_t)E_ * T_ * F_];  // compacted gatedw lo
__device__ float g_outc[(size_t)E_ * T_ * H_];   // per-expert contributions

// ---- helpers ----
__device__ __forceinline__ void split2h(float v, __half& h, __half& l) {
    h = __float2half_rn(v);
    l = __float2half_rn(v - __half2float(h));
}

#define CP16(dst_u32, src_ptr) \
    asm volatile("cp.async.cg.shared.global [%0], [%1], 16;" :: "r"(dst_u32), "l"(src_ptr))
#define CP_COMMIT asm volatile("cp.async.commit_group;")
#define CP_WAIT1  asm volatile("cp.async.wait_group 1;")

__device__ __forceinline__ uint32_t lds32(const char* p) { return *(const uint32_t*)p; }

__device__ __forceinline__ void mma16816(float* acc, uint32_t a0, uint32_t a1,
                                         uint32_t a2, uint32_t a3,
                                         uint32_t b0, uint32_t b1) {
    asm volatile(
        "mma.sync.aligned.m16n8k16.row.col.f32.f16.f16.f32 "
        "{%0,%1,%2,%3}, {%4,%5,%6,%7}, {%8,%9}, {%0,%1,%2,%3};"
        : "+f"(acc[0]), "+f"(acc[1]), "+f"(acc[2]), "+f"(acc[3])
        : "r"(a0), "r"(a1), "r"(a2), "r"(a3), "r"(b0), "r"(b1));
}

// smem stage layout (bytes): Ahi 0, Alo 12288, B 24576; stage stride 36864
// rows: 32 fp16 data (64 B) + 32 B pad = 96 B
#define STG_ 36864

// 2-term split mma over one k32 chunk (2 k16 steps), warp tile 64x64
__device__ __forceinline__ void compute_chunk(const char* st, float acc[4][8][4],
                                              int wr, int wc, int g, int q) {
    const char* A_hi = st;
    const char* A_lo = st + 12288;
    const char* B_s  = st + 24576;
    int arow[4], brow[8];
#pragma unroll
    for (int mi = 0; mi < 4; mi++) arow[mi] = (wr * 64 + mi * 16 + g) * 96;
#pragma unroll
    for (int ni = 0; ni < 8; ni++) brow[ni] = (wc * 64 + ni * 8 + g) * 96;
#pragma unroll
    for (int ks = 0; ks < 2; ks++) {
        int kb = ks * 32 + q * 4;
        uint32_t B[8][2];
#pragma unroll
        for (int ni = 0; ni < 8; ni++) {
            B[ni][0] = lds32(B_s + brow[ni] + kb);
            B[ni][1] = lds32(B_s + brow[ni] + kb + 16);
        }
        uint32_t A[4][4];
#pragma unroll
        for (int mi = 0; mi < 4; mi++) {
            A[mi][0] = lds32(A_hi + arow[mi] + kb);
            A[mi][1] = lds32(A_hi + arow[mi] + 768 + kb);
            A[mi][2] = lds32(A_hi + arow[mi] + kb + 16);
            A[mi][3] = lds32(A_hi + arow[mi] + 768 + kb + 16);
        }
#pragma unroll
        for (int ni = 0; ni < 8; ni++)       // ah * b
#pragma unroll
            for (int mi = 0; mi < 4; mi++)
                mma16816(acc[mi][ni], A[mi][0], A[mi][1], A[mi][2], A[mi][3],
                         B[ni][0], B[ni][1]);
#pragma unroll
        for (int mi = 0; mi < 4; mi++) {
            A[mi][0] = lds32(A_lo + arow[mi] + kb);
            A[mi][1] = lds32(A_lo + arow[mi] + 768 + kb);
            A[mi][2] = lds32(A_lo + arow[mi] + kb + 16);
            A[mi][3] = lds32(A_lo + arow[mi] + 768 + kb + 16);
        }
#pragma unroll
        for (int ni = 0; ni < 8; ni++)       // al * b
#pragma unroll
            for (int mi = 0; mi < 4; mi++)
                mma16816(acc[mi][ni], A[mi][0], A[mi][1], A[mi][2], A[mi][3],
                         B[ni][0], B[ni][1]);
    }
}

// ===========================================================================
// zero counters (graph replays need re-init every launch)
// ===========================================================================
__global__ void k_zero() {
    if (threadIdx.x < E_) g_cnt[threadIdx.x] = 0;
}

// ===========================================================================
// K0: routing weights + per-expert compacted token lists
// ===========================================================================
__global__ void k_route(const float* __restrict__ rw, const int* __restrict__ idx) {
    int t = blockIdx.x * blockDim.x + threadIdx.x;
    if (t >= T_) return;
    float acc[E_];
    int act[E_];
#pragma unroll
    for (int j = 0; j < E_; j++) { acc[j] = 0.0f; act[j] = 0; }
    for (int k = 0; k < TOPK_; k++) {
        int e = idx[t * TOPK_ + k];
        float v = rw[t * TOPK_ + k];
#pragma unroll
        for (int j = 0; j < E_; j++)
            if (j == e) { acc[j] += v; act[j] = 1; }
    }
#pragma unroll
    for (int j = 0; j < E_; j++) {
        g_w[j * T_ + t] = acc[j];
        int s = -1;
        if (act[j]) {
            s = atomicAdd(&g_cnt[j], 1);
            g_list[j * T_ + s] = t;
        }
        g_slot[j * T_ + t] = s;
    }
}

// ===========================================================================
// split X -> hi/lo fp16
// ===========================================================================
__global__ void k_split_x(const float* __restrict__ X) {
    int i = blockIdx.x * blockDim.x + threadIdx.x;  // one float4
    float4 v = ((const float4*)X)[i];
    __half h0, l0, h1, l1, h2, l2, h3, l3;
    split2h(v.x, h0, l0); split2h(v.y, h1, l1);
    split2h(v.z, h2, l2); split2h(v.w, h3, l3);
    __half2* ph = (__half2*)g_xhi;
    __half2* pl = (__half2*)g_xlo;
    ph[i * 2]     = __halves2half2(h0, h1);
    ph[i * 2 + 1] = __halves2half2(h2, h3);
    pl[i * 2]     = __halves2half2(l0, l1);
    pl[i * 2 + 1] = __halves2half2(l2, l3);
}

// ===========================================================================
// convert + transpose weights: src [E][RR][CC] fp32 -> dst [E][CC][RR] fp16
// ===========================================================================
__global__ void k_splitT(const float* __restrict__ src, __half* __restrict__ dst,
                         int RR, int CC) {
    __shared__ __half hs[32][36];
    int e = blockIdx.z;
    int c0 = blockIdx.x * 32, r0 = blockIdx.y * 32;
    int tx = threadIdx.x & 31, ty = threadIdx.x >> 5;
    const float* s = src + (size_t)e * RR * CC;
#pragma unroll
    for (int j = 0; j < 4; j++)
        hs[ty + 8 * j][tx] = __float2half_rn(s[(size_t)(r0 + ty + 8 * j) * CC + c0 + tx]);
    __syncthreads();
    size_t dbase = (size_t)e * RR * CC;
#pragma unroll
    for (int j = 0; j < 4; j++) {
        int cc = c0 + ty + 8 * j;
        dst[dbase + (size_t)cc * RR + r0 + tx] = hs[tx][ty + 8 * j];
    }
}

// ===========================================================================
// K1 (gathered): g_xa[e,slot,r] = x[tok,:] @ A1[e,:,r]
// ===========================================================================
__global__ void k_loraA1(const float* __restrict__ X, const float* __restrict__ A1) {
    int warp = (blockIdx.x * blockDim.x + threadIdx.x) >> 5;
    int lane = threadIdx.x & 31;
    int e = warp / T_, slot = warp % T_;
    if (slot >= g_cnt[e]) return;
    int t = g_list[e * T_ + slot];
    const float* xrow = X + (size_t)t * H_;
    float acc[R_];
#pragma unroll
    for (int r = 0; r < R_; r++) acc[r] = 0.0f;
    for (int h0 = lane * 4; h0 < H_; h0 += 128) {
        float4 xv = *(const float4*)(xrow + h0);
        const float* a = A1 + ((size_t)e * H_ + h0) * R_;
        float xs[4] = {xv.x, xv.y, xv.z, xv.w};
#pragma unroll
        for (int qd = 0; qd < 4; qd++) {
            float4 a0 = *(const float4*)(a + qd * R_);
            float4 a1 = *(const float4*)(a + qd * R_ + 4);
            acc[0] += xs[qd] * a0.x; acc[1] += xs[qd] * a0.y;
            acc[2] += xs[qd] * a0.z; acc[3] += xs[qd] * a0.w;
            acc[4] += xs[qd] * a1.x; acc[5] += xs[qd] * a1.y;
            acc[6] += xs[qd] * a1.z; acc[7] += xs[qd] * a1.w;
        }
    }
    float keep = 0.0f;
#pragma unroll
    for (int r = 0; r < R_; r++) {
        float v = acc[r];
#pragma unroll
        for (int off = 16; off; off >>= 1) v += __shfl_xor_sync(0xffffffff, v, off);
        if (lane == r) keep = v;
    }
    if (lane < R_) g_xa[(size_t)(e * T_ + slot) * R_ + lane] = keep;
}

// ===========================================================================
// K3 (gathered): g_la2[e,slot,r] = gatedw[e,slot,:] @ A2[e,:,r]
// ===========================================================================
__global__ void k_loraA2(const float* __restrict__ A2) {
    int warp = (blockIdx.x * blockDim.x + threadIdx.x) >> 5;
    int lane = threadIdx.x & 31;
    int e = warp / T_, slot = warp % T_;
    if (slot >= g_cnt[e]) return;
    const __half* ph = g_gwhi + (size_t)(e * T_ + slot) * F_;
    const __half* pl = g_gwlo + (size_t)(e * T_ + slot) * F_;
    float acc[R_];
#pragma unroll
    for (int r = 0; r < R_; r++) acc[r] = 0.0f;
    for (int f0 = lane * 4; f0 < F_; f0 += 128) {
        __half2 h0 = *(const __half2*)(ph + f0);
        __half2 h1 = *(const __half2*)(ph + f0 + 2);
        __half2 l0 = *(const __half2*)(pl + f0);
        __half2 l1 = *(const __half2*)(pl + f0 + 2);
        float xs[4] = {
            __half2float(h0.x) + __half2float(l0.x),
            __half2float(h0.y) + __half2float(l0.y),
            __half2float(h1.x) + __half2float(l1.x),
            __half2float(h1.y) + __half2float(l1.y)};
        const float* a = A2 + ((size_t)e * F_ + f0) * R_;
#pragma unroll
        for (int qd = 0; qd < 4; qd++) {
            float4 a0 = *(const float4*)(a + qd * R_);
            float4 a1 = *(const float4*)(a + qd * R_ + 4);
            acc[0] += xs[qd] * a0.x; acc[1] += xs[qd] * a0.y;
            acc[2] += xs[qd] * a0.z; acc[3] += xs[qd] * a0.w;
            acc[4] += xs[qd] * a1.x; acc[5] += xs[qd] * a1.y;
            acc[6] += xs[qd] * a1.z; acc[7] += xs[qd] * a1.w;
        }
    }
    float keep = 0.0f;
#pragma unroll
    for (int r = 0; r < R_; r++) {
        float v = acc[r];
#pragma unroll
        for (int off = 16; off; off >>= 1) v += __shfl_xor_sync(0xffffffff, v, off);
        if (lane == r) keep = v;
    }
    if (lane < R_) g_la2[(size_t)(e * T_ + slot) * R_ + lane] = keep;
}

// ===========================================================================
// K2 (gathered): HMMA GEMM1 over active tokens of expert e
// grid (D/128, 16 max m-tiles, E), 128 threads
// ===========================================================================
__global__ void __launch_bounds__(128, 2)
k_gemm1(const float* __restrict__ bias, const float* __restrict__ B1) {
    int e = blockIdx.z, m0 = blockIdx.y * 128, n0 = blockIdx.x * 128;
    int cnt = g_cnt[e];
    if (m0 >= cnt) return;
    extern __shared__ char smem[];
    uint32_t sb = (uint32_t)__cvta_generic_to_shared(smem);
    int tid = threadIdx.x;
    int wid = tid >> 5, lane = tid & 31;
    int wr = wid >> 1, wc = wid & 1, g = lane >> 2, q = lane & 3;

    int tok = g_list[e * T_ + (m0 + tid < cnt ? m0 + tid : m0)];

    float acc[4][8][4];
#pragma unroll
    for (int a = 0; a < 4; a++)
#pragma unroll
        for (int b = 0; b < 8; b++)
#pragma unroll
            for (int c = 0; c < 4; c++) acc[a][b][c] = 0.0f;

    auto issue = [&](int c, int stage) {
        int k0 = c * 32;
        uint32_t a_hi = sb + stage * STG_ + tid * 96;
        const __half* sxh = g_xhi + (size_t)tok * H_ + k0;
        const __half* sxl = g_xlo + (size_t)tok * H_ + k0;
        const __half* swh = g_w1h + ((size_t)e * D_ + n0 + tid) * H_ + k0;
#pragma unroll
        for (int j = 0; j < 4; j++) {
            CP16(a_hi + j * 16,         sxh + j * 8);
            CP16(a_hi + 12288 + j * 16, sxl + j * 8);
            CP16(a_hi + 24576 + j * 16, swh + j * 8);
        }
    };
    issue(0, 0); CP_COMMIT;
    issue(1, 1); CP_COMMIT;
    const int NCH = H_ / 32;
    for (int c = 0; c < NCH; c++) {
        CP_WAIT1;
        __syncthreads();
        compute_chunk(smem + (c & 1) * STG_, acc, wr, wc, g, q);
        __syncthreads();
        if (c + 2 < NCH) issue(c + 2, c & 1);
        CP_COMMIT;
    }

    // ---- epilogue ----
    float* xa_s   = (float*)smem;            // [128][8]
    float* b1_s   = (float*)(smem + 4096);   // [8][128]
    float* bias_s = (float*)(smem + 8192);   // [128]
    float* w_s    = (float*)(smem + 8704);   // [128]
    for (int i = tid; i < 1024; i += 128) {
        xa_s[i] = g_xa[((size_t)e * T_ + m0 + (i >> 3)) * 8 + (i & 7)] * SCALING_;
        b1_s[i] = B1[((size_t)e * 8 + (i >> 7)) * D_ + n0 + (i & 127)];
    }
    bias_s[tid] = bias[(size_t)e * D_ + n0 + tid];
    w_s[tid] = (m0 + tid < cnt) ? g_w[e * T_ + tok] : 0.0f;
    __syncthreads();

#pragma unroll
    for (int mi = 0; mi < 4; mi++) {
#pragma unroll
        for (int ni = 0; ni < 8; ni++) {
            int c = wc * 64 + ni * 8 + q * 2;
            float2 bia = *(const float2*)&bias_s[c];
#pragma unroll
            for (int h = 0; h < 2; h++) {
                int row = wr * 64 + mi * 16 + g + h * 8;
                if (m0 + row >= cnt) continue;
                float gate = acc[mi][ni][h * 2 + 0] + bia.x;
                float up   = acc[mi][ni][h * 2 + 1] + bia.y;
                const float* xr = &xa_s[row * 8];
#pragma unroll
                for (int p = 0; p < 8; p++) {
                    float2 b1v = *(const float2*)&b1_s[p * 128 + c];
                    gate += xr[p] * b1v.x;
                    up   += xr[p] * b1v.y;
                }
                gate = fminf(gate, LIMIT_);
                up = fminf(fmaxf(up, -LIMIT_), LIMIT_);
                float glu = gate / (1.0f + expf(-ACT_ALPHA_ * gate));
                float val = w_s[row] * (up + 1.0f) * glu;
                __half hh, ll; split2h(val, hh, ll);
                size_t oidx = ((size_t)e * T_ + m0 + row) * F_ + ((n0 + c) >> 1);
                g_gwhi[oidx] = hh; g_gwlo[oidx] = ll;
            }
        }
    }
}

// ===========================================================================
// K4 (gathered): per-expert HMMA GEMM2 -> g_outc[e][slot][h]
// grid (H/128, 16 max m-tiles, E), 128 threads
// ===========================================================================
__global__ void __launch_bounds__(128, 2)
k_gemm2(const float* __restrict__ bias2, const float* __restrict__ B2) {
    int e = blockIdx.z, m0 = blockIdx.y * 128, n0 = blockIdx.x * 128;
    int cnt = g_cnt[e];
    if (m0 >= cnt) return;
    extern __shared__ char smem[];
    uint32_t sb = (uint32_t)__cvta_generic_to_shared(smem);
    int tid = threadIdx.x;
    int wid = tid >> 5, lane = tid & 31;
    int wr = wid >> 1, wc = wid & 1, g = lane >> 2, q = lane & 3;

    float acc[4][8][4];
#pragma unroll
    for (int a = 0; a < 4; a++)
#pragma unroll
        for (int b = 0; b < 8; b++)
#pragma unroll
            for (int c = 0; c < 4; c++) acc[a][b][c] = 0.0f;

    auto issue = [&](int c, int stage) {
        int f0 = c * 32;
        uint32_t a_hi = sb + stage * STG_ + tid * 96;
        const __half* sah = g_gwhi + ((size_t)e * T_ + m0 + tid) * F_ + f0;
        const __half* sal = g_gwlo + ((size_t)e * T_ + m0 + tid) * F_ + f0;
        const __half* sbh = g_w2h + ((size_t)e * H_ + n0 + tid) * F_ + f0;
#pragma unroll
        for (int j = 0; j < 4; j++) {
            CP16(a_hi + j * 16,         sah + j * 8);
            CP16(a_hi + 12288 + j * 16, sal + j * 8);
            CP16(a_hi + 24576 + j * 16, sbh + j * 8);
        }
    };
    issue(0, 0); CP_COMMIT;
    issue(1, 1); CP_COMMIT;
    const int NCH = F_ / 32;
    for (int c = 0; c < NCH; c++) {
        CP_WAIT1;
        __syncthreads();
        compute_chunk(smem + (c & 1) * STG_, acc, wr, wc, g, q);
        __syncthreads();
        if (c + 2 < NCH) issue(c + 2, c & 1);
        CP_COMMIT;
    }

    // ---- epilogue: += SCALING*la2@B2 + w*bias2; store to outc ----
    float* la_s = (float*)smem;            // [128][8]
    float* b2_s = (float*)(smem + 4096);   // [8][128]
    float* bb_s = (float*)(smem + 8192);   // [128]
    float* w_s  = (float*)(smem + 8704);   // [128]
    for (int i = tid; i < 1024; i += 128) {
        la_s[i] = g_la2[((size_t)e * T_ + m0 + (i >> 3)) * 8 + (i & 7)] * SCALING_;
        b2_s[i] = B2[((size_t)e * 8 + (i >> 7)) * H_ + n0 + (i & 127)];
    }
    bb_s[tid] = bias2[(size_t)e * H_ + n0 + tid];
    {
        int gs = m0 + tid;
        w_s[tid] = (gs < cnt) ? g_w[e * T_ + g_list[e * T_ + gs]] : 0.0f;
    }
    __syncthreads();

#pragma unroll
    for (int mi = 0; mi < 4; mi++) {
#pragma unroll
        for (int ni = 0; ni < 8; ni++) {
            int c = wc * 64 + ni * 8 + q * 2;
            float2 bb = *(const float2*)&bb_s[c];
#pragma unroll
            for (int h = 0; h < 2; h++) {
                int row = wr * 64 + mi * 16 + g + h * 8;
                if (m0 + row >= cnt) continue;
                float v0 = acc[mi][ni][h * 2 + 0];
                float v1 = acc[mi][ni][h * 2 + 1];
                const float* la = &la_s[row * 8];
#pragma unroll
                for (int p = 0; p < 8; p++) {
                    float2 bv = *(const float2*)&b2_s[p * 128 + c];
                    v0 += la[p] * bv.x;
                    v1 += la[p] * bv.y;
                }
                float wt = w_s[row];
                v0 += wt * bb.x;
                v1 += wt * bb.y;
                *(float2*)(g_outc + ((size_t)e * T_ + m0 + row) * H_ + n0 + c) =
                    make_float2(v0, v1);
            }
        }
    }
}

// ===========================================================================
// K5: combine per-expert contributions -> out
// ===========================================================================
__global__ void __launch_bounds__(128)
k_combine(float* __restrict__ out) {
    int t = blockIdx.x;
    int tid = threadIdx.x;
    int slots[E_];
#pragma unroll
    for (int e = 0; e < E_; e++) slots[e] = g_slot[e * T_ + t];
#pragma unroll
    for (int k = 0; k < 4; k++) {
        int h = tid * 4 + k * 512;
        float4 acc = make_float4(0.f, 0.f, 0.f, 0.f);
#pragma unroll
        for (int e = 0; e < E_; e++) {
            int s = slots[e];
            if (s >= 0) {
                float4 v = *(const float4*)(g_outc + ((size_t)e * T_ + s) * H_ + h);
                acc.x += v.x; acc.y += v.y; acc.z += v.z; acc.w += v.w;
            }
        }
        *(float4*)(out + (size_t)t * H_ + h) = acc;
    }
}

// ===========================================================================
extern "C" void kernel_launch(void* const* d_in, const int* in_sizes, int n_in,
                              void* d_out, int out_size) {
    const float* x      = (const float*)d_in[0];
    const float* rw     = (const float*)d_in[1];
    const float* gup    = (const float*)d_in[2];
    const float* gup_b  = (const float*)d_in[3];
    const float* dn     = (const float*)d_in[4];
    const float* dn_b   = (const float*)d_in[5];
    const float* A1     = (const float*)d_in[6];
    const float* B1     = (const float*)d_in[7];
    const float* A2     = (const float*)d_in[8];
    const float* B2     = (const float*)d_in[9];
    const int*   ri     = (const int*)d_in[10];   // int32 (JAX x64 off)
    float* out = (float*)d_out;

    static bool attr_done = false;
    if (!attr_done) {
        cudaFuncSetAttribute(k_gemm1, cudaFuncAttributeMaxDynamicSharedMemorySize, 2 * STG_);
        cudaFuncSetAttribute(k_gemm2, cudaFuncAttributeMaxDynamicSharedMemorySize, 2 * STG_);
        attr_done = true;
    }

    __half *w1h, *w2h;
    cudaGetSymbolAddress((void**)&w1h, g_w1h);
    cudaGetSymbolAddress((void**)&w2h, g_w2h);

    k_zero<<<1, 32>>>();
    k_route<<<(T_ + 127) / 128, 128>>>(rw, ri);
    k_split_x<<<(T_ * H_ / 4) / 256, 256>>>(x);
    k_splitT<<<dim3(D_ / 32, H_ / 32, E_), 256>>>(gup, w1h, H_, D_);
    k_splitT<<<dim3(H_ / 32, F_ / 32, E_), 256>>>(dn, w2h, F_, H_);
    k_loraA1<<<(E_ * T_) / 8, 256>>>(x, A1);
    k_gemm1<<<dim3(D_ / 128, T_ / 128, E_), 128, 2 * STG_>>>(gup_b, B1);
    k_loraA2<<<(E_ * T_) / 8, 256>>>(A2);
    k_gemm2<<<dim3(H_ / 128, T_ / 128, E_), 128, 2 * STG_>>>(dn_b, B2);
    k_combine<<<T_, 128>>>(out);
}